// round 5
// baseline (speedup 1.0000x reference)
#include <cuda_runtime.h>
#include <cuda_bf16.h>
#include <cstdint>

#define N_NODES 50000
#define N_EDGES 800000
#define IN_DIM  128
#define OUT_DIM 64

// ---------------------------------------------------------------------------
// static device scratch (no allocs allowed)
// ---------------------------------------------------------------------------
__device__ float g_hidden[N_NODES * OUT_DIM];   // 12.8 MB
__device__ int   g_deg[N_NODES];
__device__ int   g_pos[N_NODES];
__device__ int   g_off[N_NODES];
__device__ int2  g_edge[N_EDGES];               // {col, val-as-int} sorted by row

#define SCAN_BLOCK 256
#define N_SCAN_BLOCKS ((N_NODES + SCAN_BLOCK - 1) / SCAN_BLOCK)   // 196
__device__ int g_blocksum[N_SCAN_BLOCKS];

// ---------------------------------------------------------------------------
// packed f32x2 helpers
// ---------------------------------------------------------------------------
__device__ __forceinline__ unsigned long long dup2(float v) {
    unsigned long long r;
    asm("mov.b64 %0, {%1, %1};" : "=l"(r) : "f"(v));
    return r;
}
#define FMA2(acc, a, b) \
    asm("fma.rn.f32x2 %0, %1, %2, %0;" : "+l"(acc) : "l"(a), "l"(b))

// ---------------------------------------------------------------------------
// CSR build step 0: zero deg + pos
// ---------------------------------------------------------------------------
__global__ void zero_kernel() {
    int i = blockIdx.x * blockDim.x + threadIdx.x;
    if (i < N_NODES) { g_deg[i] = 0; g_pos[i] = 0; }
}

// CSR build step 1: row histogram
__global__ void hist_kernel(const int* __restrict__ edge_row) {
    int e = blockIdx.x * blockDim.x + threadIdx.x;
    if (e < N_EDGES) atomicAdd(&g_deg[edge_row[e]], 1);
}

// CSR build step 2a: per-block sums of deg
__global__ void scan_reduce_kernel() {
    __shared__ int s[SCAN_BLOCK];
    int i = blockIdx.x * SCAN_BLOCK + threadIdx.x;
    s[threadIdx.x] = (i < N_NODES) ? g_deg[i] : 0;
    __syncthreads();
    #pragma unroll
    for (int ofs = SCAN_BLOCK / 2; ofs > 0; ofs >>= 1) {
        if (threadIdx.x < ofs) s[threadIdx.x] += s[threadIdx.x + ofs];
        __syncthreads();
    }
    if (threadIdx.x == 0) g_blocksum[blockIdx.x] = s[0];
}

// CSR build step 2b: exclusive scan of block sums (single block)
__global__ void scan_blocksums_kernel() {
    __shared__ int s[SCAN_BLOCK];
    int t = threadIdx.x;
    int v = (t < N_SCAN_BLOCKS) ? g_blocksum[t] : 0;
    s[t] = v;
    __syncthreads();
    for (int ofs = 1; ofs < SCAN_BLOCK; ofs <<= 1) {
        int add = (t >= ofs) ? s[t - ofs] : 0;
        __syncthreads();
        s[t] += add;
        __syncthreads();
    }
    if (t < N_SCAN_BLOCKS) g_blocksum[t] = s[t] - v;   // exclusive
}

// CSR build step 2c: per-element exclusive scan + block offset -> g_off
__global__ void scan_final_kernel() {
    __shared__ int s[SCAN_BLOCK];
    int t = threadIdx.x;
    int i = blockIdx.x * SCAN_BLOCK + t;
    int v = (i < N_NODES) ? g_deg[i] : 0;
    s[t] = v;
    __syncthreads();
    for (int ofs = 1; ofs < SCAN_BLOCK; ofs <<= 1) {
        int add = (t >= ofs) ? s[t - ofs] : 0;
        __syncthreads();
        s[t] += add;
        __syncthreads();
    }
    if (i < N_NODES) g_off[i] = g_blocksum[blockIdx.x] + s[t] - v;
}

// CSR build step 3: bucket fill (packed {col, val})
__global__ void fill_kernel(const int* __restrict__ edge_row,
                            const int* __restrict__ edge_col,
                            const float* __restrict__ edge_val) {
    int e = blockIdx.x * blockDim.x + threadIdx.x;
    if (e < N_EDGES) {
        int r = edge_row[e];
        int p = g_off[r] + atomicAdd(&g_pos[r], 1);
        g_edge[p] = make_int2(edge_col[e], __float_as_int(edge_val[e]));
    }
}

// ---------------------------------------------------------------------------
// hidden = x @ w  — register-tiled, packed f32x2 FMA (unchanged from R4)
// ---------------------------------------------------------------------------
#define GEMM_ROWS 128
#define GEMM_THREADS 128
#define XROW(r) ((r) * IN_DIM + ((((r) >> 3) & 3) << 2) + (((r) >> 5) << 4))
#define XS_FLOATS (XROW(GEMM_ROWS - 1) + IN_DIM + 16)
#define WS_FLOATS (IN_DIM * OUT_DIM)
#define GEMM_SMEM_BYTES ((WS_FLOATS + XS_FLOATS) * 4)

__global__ void __launch_bounds__(GEMM_THREADS)
gemm_kernel(const float* __restrict__ x, const float* __restrict__ w) {
    extern __shared__ float smem[];
    float* ws = smem;
    float* xs = smem + WS_FLOATS;

    int tid  = threadIdx.x;
    int warp = tid >> 5;
    int lane = tid & 31;
    int pg   = lane & 7;
    int rg   = lane >> 3;
    int bb   = blockIdx.x * GEMM_ROWS;

    {
        const float4* w4 = reinterpret_cast<const float4*>(w);
        float4* ws4 = reinterpret_cast<float4*>(ws);
        #pragma unroll
        for (int i = 0; i < WS_FLOATS / 4 / GEMM_THREADS; i++) {
            int c = i * GEMM_THREADS + tid;
            ws4[c] = w4[c];
        }
    }
    {
        const float4* x4 = reinterpret_cast<const float4*>(x);
        #pragma unroll
        for (int i = 0; i < (GEMM_ROWS * IN_DIM / 4) / GEMM_THREADS; i++) {
            int c  = i * GEMM_THREADS + tid;
            int r  = c >> 5;
            int k4 = c & 31;
            int grow = bb + r;
            float4 v = (grow < N_NODES) ? x4[(size_t)grow * (IN_DIM / 4) + k4]
                                        : make_float4(0.f, 0.f, 0.f, 0.f);
            *reinterpret_cast<float4*>(&xs[XROW(r) + k4 * 4]) = v;
        }
    }
    __syncthreads();

    unsigned long long acc[8][4];
    #pragma unroll
    for (int j = 0; j < 8; j++)
        #pragma unroll
        for (int p = 0; p < 4; p++) acc[j][p] = 0ull;

    int wrb = warp * 32 + rg * 8;
    uint32_t ws_base = (uint32_t)__cvta_generic_to_shared(ws) + (uint32_t)(pg * 32);
    const float* xrow0 = xs + XROW(wrb);

    #pragma unroll 4
    for (int k = 0; k < IN_DIM; k++) {
        unsigned long long wpa, wpb, wpc, wpd;
        uint32_t wa = ws_base + (uint32_t)(k * (OUT_DIM * 4));
        asm("ld.shared.v2.b64 {%0, %1}, [%2];" : "=l"(wpa), "=l"(wpb) : "r"(wa));
        asm("ld.shared.v2.b64 {%0, %1}, [%2];" : "=l"(wpc), "=l"(wpd) : "r"(wa + 16));

        #pragma unroll
        for (int j = 0; j < 8; j++) {
            unsigned long long xp = dup2(xrow0[j * IN_DIM + k]);
            FMA2(acc[j][0], xp, wpa);
            FMA2(acc[j][1], xp, wpb);
            FMA2(acc[j][2], xp, wpc);
            FMA2(acc[j][3], xp, wpd);
        }
    }

    #pragma unroll
    for (int j = 0; j < 8; j++) {
        int grow = bb + wrb + j;
        if (grow < N_NODES) {
            float2 a0 = *reinterpret_cast<float2*>(&acc[j][0]);
            float2 a1 = *reinterpret_cast<float2*>(&acc[j][1]);
            float2 a2 = *reinterpret_cast<float2*>(&acc[j][2]);
            float2 a3 = *reinterpret_cast<float2*>(&acc[j][3]);
            float4* dst = reinterpret_cast<float4*>(g_hidden + (size_t)grow * OUT_DIM + pg * 8);
            dst[0] = make_float4(a0.x, a0.y, a1.x, a1.y);
            dst[1] = make_float4(a2.x, a2.y, a3.x, a3.y);
        }
    }
}

// ---------------------------------------------------------------------------
// Fused accumulate + bias + relu.  One warp per node, lane owns 2 cols.
// Edges chunk-loaded (32 at a time) and broadcast via shfl.  No atomics.
// ---------------------------------------------------------------------------
__global__ void __launch_bounds__(256)
accum_kernel(float* __restrict__ out, const float* __restrict__ b) {
    int node = (blockIdx.x * blockDim.x + threadIdx.x) >> 5;
    int lane = threadIdx.x & 31;
    if (node >= N_NODES) return;

    int off = g_off[node];
    int deg = g_deg[node];

    float accx = 0.f, accy = 0.f;

    for (int base = 0; base < deg; base += 32) {
        int  rem = deg - base;
        int  n   = rem < 32 ? rem : 32;
        int2 ev  = (lane < n) ? g_edge[off + base + lane] : make_int2(0, 0);

        for (int j = 0; j < n; j++) {
            int   col = __shfl_sync(0xffffffffu, ev.x, j);
            float val = __int_as_float(__shfl_sync(0xffffffffu, ev.y, j));
            float2 hv = *reinterpret_cast<const float2*>(
                            g_hidden + (size_t)col * OUT_DIM + lane * 2);
            accx = fmaf(val, hv.x, accx);
            accy = fmaf(val, hv.y, accy);
        }
    }

    float2 bv = reinterpret_cast<const float2*>(b)[lane];
    accx = fmaxf(accx + bv.x, 0.f);
    accy = fmaxf(accy + bv.y, 0.f);
    *reinterpret_cast<float2*>(out + (size_t)node * OUT_DIM + lane * 2)
        = make_float2(accx, accy);
}

// ---------------------------------------------------------------------------
extern "C" void kernel_launch(void* const* d_in, const int* in_sizes, int n_in,
                              void* d_out, int out_size) {
    const float* x        = (const float*)d_in[0];
    const int*   edge_row = (const int*)  d_in[1];
    const int*   edge_col = (const int*)  d_in[2];
    const float* edge_val = (const float*)d_in[3];
    const float* w        = (const float*)d_in[4];
    const float* b        = (const float*)d_in[5];
    float* out = (float*)d_out;

    cudaFuncSetAttribute(gemm_kernel,
                         cudaFuncAttributeMaxDynamicSharedMemorySize,
                         GEMM_SMEM_BYTES);

    // GEMM first (independent of CSR build; stream-serialized anyway)
    gemm_kernel<<<(N_NODES + GEMM_ROWS - 1) / GEMM_ROWS, GEMM_THREADS,
                  GEMM_SMEM_BYTES>>>(x, w);

    // CSR build
    zero_kernel<<<(N_NODES + 255) / 256, 256>>>();
    hist_kernel<<<(N_EDGES + 255) / 256, 256>>>(edge_row);
    scan_reduce_kernel<<<N_SCAN_BLOCKS, SCAN_BLOCK>>>();
    scan_blocksums_kernel<<<1, SCAN_BLOCK>>>();
    scan_final_kernel<<<N_SCAN_BLOCKS, SCAN_BLOCK>>>();
    fill_kernel<<<(N_EDGES + 255) / 256, 256>>>(edge_row, edge_col, edge_val);

    // fused SpMM + bias + relu (one warp per node)
    accum_kernel<<<(N_NODES * 32 + 255) / 256, 256>>>(out, b);
}

// round 6
// speedup vs baseline: 1.0282x; 1.0282x over previous
#include <cuda_runtime.h>
#include <cuda_bf16.h>
#include <cstdint>

#define N_NODES 50000
#define N_EDGES 800000
#define IN_DIM  128
#define OUT_DIM 64

// ---------------------------------------------------------------------------
// static device scratch (no allocs allowed)
// ---------------------------------------------------------------------------
__device__ float g_hidden[N_NODES * OUT_DIM];   // 12.8 MB
__device__ int   g_deg[N_NODES];
__device__ int   g_pos[N_NODES];                // running fill cursor (init = off)
__device__ int   g_off[N_NODES];
__device__ int2  g_edge[N_EDGES];               // {col, val-as-int} grouped by row

#define SCAN_BLOCK 256
#define N_SCAN_BLOCKS ((N_NODES + SCAN_BLOCK - 1) / SCAN_BLOCK)   // 196
__device__ int g_blocksum[N_SCAN_BLOCKS];

// ---------------------------------------------------------------------------
// packed f32x2 helpers
// ---------------------------------------------------------------------------
__device__ __forceinline__ unsigned long long dup2(float v) {
    unsigned long long r;
    asm("mov.b64 %0, {%1, %1};" : "=l"(r) : "f"(v));
    return r;
}
#define FMA2(acc, a, b) \
    asm("fma.rn.f32x2 %0, %1, %2, %0;" : "+l"(acc) : "l"(a), "l"(b))

// ---------------------------------------------------------------------------
// Kernel 1: hidden = x @ w  — register-tiled, packed f32x2 FMA.
// ALSO zeroes g_deg (kernel boundary orders it before hist).
// ---------------------------------------------------------------------------
#define GEMM_ROWS 128
#define GEMM_THREADS 128
#define XROW(r) ((r) * IN_DIM + ((((r) >> 3) & 3) << 2) + (((r) >> 5) << 4))
#define XS_FLOATS (XROW(GEMM_ROWS - 1) + IN_DIM + 16)
#define WS_FLOATS (IN_DIM * OUT_DIM)
#define GEMM_SMEM_BYTES ((WS_FLOATS + XS_FLOATS) * 4)
#define GEMM_GRID ((N_NODES + GEMM_ROWS - 1) / GEMM_ROWS)   // 391

__global__ void __launch_bounds__(GEMM_THREADS)
gemm_kernel(const float* __restrict__ x, const float* __restrict__ w) {
    extern __shared__ float smem[];
    float* ws = smem;
    float* xs = smem + WS_FLOATS;

    int tid  = threadIdx.x;
    int warp = tid >> 5;
    int lane = tid & 31;
    int pg   = lane & 7;
    int rg   = lane >> 3;
    int bb   = blockIdx.x * GEMM_ROWS;

    // fold in: zero g_deg (391*128 = 50048 >= 50000)
    {
        int gtid = blockIdx.x * GEMM_THREADS + tid;
        if (gtid < N_NODES) g_deg[gtid] = 0;
    }

    {
        const float4* w4 = reinterpret_cast<const float4*>(w);
        float4* ws4 = reinterpret_cast<float4*>(ws);
        #pragma unroll
        for (int i = 0; i < WS_FLOATS / 4 / GEMM_THREADS; i++) {
            int c = i * GEMM_THREADS + tid;
            ws4[c] = w4[c];
        }
    }
    {
        const float4* x4 = reinterpret_cast<const float4*>(x);
        #pragma unroll
        for (int i = 0; i < (GEMM_ROWS * IN_DIM / 4) / GEMM_THREADS; i++) {
            int c  = i * GEMM_THREADS + tid;
            int r  = c >> 5;
            int k4 = c & 31;
            int grow = bb + r;
            float4 v = (grow < N_NODES) ? x4[(size_t)grow * (IN_DIM / 4) + k4]
                                        : make_float4(0.f, 0.f, 0.f, 0.f);
            *reinterpret_cast<float4*>(&xs[XROW(r) + k4 * 4]) = v;
        }
    }
    __syncthreads();

    unsigned long long acc[8][4];
    #pragma unroll
    for (int j = 0; j < 8; j++)
        #pragma unroll
        for (int p = 0; p < 4; p++) acc[j][p] = 0ull;

    int wrb = warp * 32 + rg * 8;
    uint32_t ws_base = (uint32_t)__cvta_generic_to_shared(ws) + (uint32_t)(pg * 32);
    const float* xrow0 = xs + XROW(wrb);

    #pragma unroll 4
    for (int k = 0; k < IN_DIM; k++) {
        unsigned long long wpa, wpb, wpc, wpd;
        uint32_t wa = ws_base + (uint32_t)(k * (OUT_DIM * 4));
        asm("ld.shared.v2.b64 {%0, %1}, [%2];" : "=l"(wpa), "=l"(wpb) : "r"(wa));
        asm("ld.shared.v2.b64 {%0, %1}, [%2];" : "=l"(wpc), "=l"(wpd) : "r"(wa + 16));

        #pragma unroll
        for (int j = 0; j < 8; j++) {
            unsigned long long xp = dup2(xrow0[j * IN_DIM + k]);
            FMA2(acc[j][0], xp, wpa);
            FMA2(acc[j][1], xp, wpb);
            FMA2(acc[j][2], xp, wpc);
            FMA2(acc[j][3], xp, wpd);
        }
    }

    #pragma unroll
    for (int j = 0; j < 8; j++) {
        int grow = bb + wrb + j;
        if (grow < N_NODES) {
            float2 a0 = *reinterpret_cast<float2*>(&acc[j][0]);
            float2 a1 = *reinterpret_cast<float2*>(&acc[j][1]);
            float2 a2 = *reinterpret_cast<float2*>(&acc[j][2]);
            float2 a3 = *reinterpret_cast<float2*>(&acc[j][3]);
            float4* dst = reinterpret_cast<float4*>(g_hidden + (size_t)grow * OUT_DIM + pg * 8);
            dst[0] = make_float4(a0.x, a0.y, a1.x, a1.y);
            dst[1] = make_float4(a2.x, a2.y, a3.x, a3.y);
        }
    }
}

// ---------------------------------------------------------------------------
// Kernel 2: row histogram (int4 edge loads, 4 edges per thread)
// ---------------------------------------------------------------------------
__global__ void hist_kernel(const int* __restrict__ edge_row) {
    int i = blockIdx.x * blockDim.x + threadIdx.x;      // int4 index
    if (i < N_EDGES / 4) {
        int4 r4 = reinterpret_cast<const int4*>(edge_row)[i];
        atomicAdd(&g_deg[r4.x], 1);
        atomicAdd(&g_deg[r4.y], 1);
        atomicAdd(&g_deg[r4.z], 1);
        atomicAdd(&g_deg[r4.w], 1);
    }
}

// ---------------------------------------------------------------------------
// Kernel 3: per-block reduce of degrees -> g_blocksum
// ---------------------------------------------------------------------------
__global__ void scan_reduce_kernel() {
    __shared__ int s[SCAN_BLOCK];
    int i = blockIdx.x * SCAN_BLOCK + threadIdx.x;
    s[threadIdx.x] = (i < N_NODES) ? g_deg[i] : 0;
    __syncthreads();
    #pragma unroll
    for (int ofs = SCAN_BLOCK / 2; ofs > 0; ofs >>= 1) {
        if (threadIdx.x < ofs) s[threadIdx.x] += s[threadIdx.x + ofs];
        __syncthreads();
    }
    if (threadIdx.x == 0) g_blocksum[blockIdx.x] = s[0];
}

// ---------------------------------------------------------------------------
// Kernel 4: fused apply — every block redundantly scans the 196 block sums
// in smem (cheap), then does its local exclusive scan; writes g_off AND
// g_pos (= off, so fill needs no separate zero/add).
// ---------------------------------------------------------------------------
__global__ void scan_apply_kernel() {
    __shared__ int bs[SCAN_BLOCK];
    __shared__ int s[SCAN_BLOCK];
    int t = threadIdx.x;

    // scan of block sums (Hillis-Steele inclusive over 256 slots)
    int bv = (t < N_SCAN_BLOCKS) ? g_blocksum[t] : 0;
    bs[t] = bv;
    __syncthreads();
    for (int ofs = 1; ofs < SCAN_BLOCK; ofs <<= 1) {
        int add = (t >= ofs) ? bs[t - ofs] : 0;
        __syncthreads();
        bs[t] += add;
        __syncthreads();
    }
    // exclusive prefix of this block
    int block_prefix = bs[blockIdx.x] -
        ((blockIdx.x < N_SCAN_BLOCKS) ? g_blocksum[blockIdx.x] : 0);

    // local exclusive scan of this block's degrees
    int i = blockIdx.x * SCAN_BLOCK + t;
    int v = (i < N_NODES) ? g_deg[i] : 0;
    s[t] = v;
    __syncthreads();
    for (int ofs = 1; ofs < SCAN_BLOCK; ofs <<= 1) {
        int add = (t >= ofs) ? s[t - ofs] : 0;
        __syncthreads();
        s[t] += add;
        __syncthreads();
    }
    if (i < N_NODES) {
        int off = block_prefix + s[t] - v;
        g_off[i] = off;
        g_pos[i] = off;
    }
}

// ---------------------------------------------------------------------------
// Kernel 5: bucket fill (packed {col, val}); cursor = g_pos (pre-set to off)
// ---------------------------------------------------------------------------
__global__ void fill_kernel(const int* __restrict__ edge_row,
                            const int* __restrict__ edge_col,
                            const float* __restrict__ edge_val) {
    int e = blockIdx.x * blockDim.x + threadIdx.x;
    if (e < N_EDGES) {
        int r = edge_row[e];
        int p = atomicAdd(&g_pos[r], 1);
        g_edge[p] = make_int2(edge_col[e], __float_as_int(edge_val[e]));
    }
}

// ---------------------------------------------------------------------------
// Kernel 6: fused accumulate + bias + relu.  One warp per node, lane owns
// 2 cols.  Full 32-edge chunks use a constant-bound unrolled loop so ptxas
// front-batches the 32 independent LDG.64 gathers (MLP >> 1).
// ---------------------------------------------------------------------------
__global__ void __launch_bounds__(256)
accum_kernel(float* __restrict__ out, const float* __restrict__ b) {
    int node = (blockIdx.x * blockDim.x + threadIdx.x) >> 5;
    int lane = threadIdx.x & 31;
    if (node >= N_NODES) return;

    int off = g_off[node];
    int deg = g_deg[node];

    float accx = 0.f, accy = 0.f;
    const float* hbase = g_hidden + lane * 2;

    int base = 0;
    int full = deg & ~31;
    for (; base < full; base += 32) {
        int2 ev = g_edge[off + base + lane];
        #pragma unroll
        for (int j = 0; j < 32; j++) {
            int   col = __shfl_sync(0xffffffffu, ev.x, j);
            float val = __int_as_float(__shfl_sync(0xffffffffu, ev.y, j));
            float2 hv = *reinterpret_cast<const float2*>(hbase + (size_t)col * OUT_DIM);
            accx = fmaf(val, hv.x, accx);
            accy = fmaf(val, hv.y, accy);
        }
    }
    int rem = deg - base;
    if (rem > 0) {
        int2 ev = (lane < rem) ? g_edge[off + base + lane] : make_int2(0, 0);
        for (int j = 0; j < rem; j++) {
            int   col = __shfl_sync(0xffffffffu, ev.x, j);
            float val = __int_as_float(__shfl_sync(0xffffffffu, ev.y, j));
            float2 hv = *reinterpret_cast<const float2*>(hbase + (size_t)col * OUT_DIM);
            accx = fmaf(val, hv.x, accx);
            accy = fmaf(val, hv.y, accy);
        }
    }

    float2 bv = reinterpret_cast<const float2*>(b)[lane];
    accx = fmaxf(accx + bv.x, 0.f);
    accy = fmaxf(accy + bv.y, 0.f);
    *reinterpret_cast<float2*>(out + (size_t)node * OUT_DIM + lane * 2)
        = make_float2(accx, accy);
}

// ---------------------------------------------------------------------------
extern "C" void kernel_launch(void* const* d_in, const int* in_sizes, int n_in,
                              void* d_out, int out_size) {
    const float* x        = (const float*)d_in[0];
    const int*   edge_row = (const int*)  d_in[1];
    const int*   edge_col = (const int*)  d_in[2];
    const float* edge_val = (const float*)d_in[3];
    const float* w        = (const float*)d_in[4];
    const float* b        = (const float*)d_in[5];
    float* out = (float*)d_out;

    cudaFuncSetAttribute(gemm_kernel,
                         cudaFuncAttributeMaxDynamicSharedMemorySize,
                         GEMM_SMEM_BYTES);

    gemm_kernel<<<GEMM_GRID, GEMM_THREADS, GEMM_SMEM_BYTES>>>(x, w);  // + zero g_deg
    hist_kernel<<<(N_EDGES / 4 + 255) / 256, 256>>>(edge_row);
    scan_reduce_kernel<<<N_SCAN_BLOCKS, SCAN_BLOCK>>>();
    scan_apply_kernel<<<N_SCAN_BLOCKS, SCAN_BLOCK>>>();
    fill_kernel<<<(N_EDGES + 255) / 256, 256>>>(edge_row, edge_col, edge_val);
    accum_kernel<<<(N_NODES * 32 + 255) / 256, 256>>>(out, b);
}